// round 1
// baseline (speedup 1.0000x reference)
#include <cuda_runtime.h>
#include <cuda_bf16.h>
#include <math.h>

// Problem constants (fixed shapes from reference)
#define NN 50000
#define EE 300000
#define DD 256
#define FF 1024
#define CC 40

// ---------------- device scratch (no allocations allowed) ----------------
__device__ float g_x[NN * DD];       // current features
__device__ float g_m[NN * DD];       // SpMM output
__device__ float g_norm_s[NN];
__device__ float g_norm_d[NN];
__device__ int   g_deg_out[NN];
__device__ int   g_deg_in[NN];       // also the CSR histogram (by dst)
__device__ int   g_rowptr[NN + 1];
__device__ int   g_cursor[NN];
__device__ int   g_col[EE];          // CSR column (src) indices, grouped by dst
__device__ int   g_blocksums[128];
__device__ float g_colsum[DD];
__device__ float g_colsq[DD];

// ---------------- small utility kernels ----------------
__global__ void zero_init_kernel() {
    int i = blockIdx.x * blockDim.x + threadIdx.x;
    if (i < NN) { g_deg_out[i] = 0; g_deg_in[i] = 0; g_cursor[i] = 0; }
}

__global__ void zero_bn_kernel() {
    int t = threadIdx.x;
    if (t < DD) { g_colsum[t] = 0.f; g_colsq[t] = 0.f; }
}

__global__ void count_deg_kernel(const int* __restrict__ src, const int* __restrict__ dst) {
    int e = blockIdx.x * blockDim.x + threadIdx.x;
    if (e < EE) {
        atomicAdd(&g_deg_out[src[e]], 1);
        atomicAdd(&g_deg_in[dst[e]], 1);
    }
}

__global__ void norms_kernel() {
    int i = blockIdx.x * blockDim.x + threadIdx.x;
    if (i < NN) {
        g_norm_s[i] = rsqrtf(fmaxf((float)g_deg_out[i], 1.f));
        g_norm_d[i] = rsqrtf(fmaxf((float)g_deg_in[i], 1.f));
    }
}

// ---------------- exclusive scan of g_deg_in -> g_rowptr ----------------
#define SCAN_CHUNK 512
__global__ void scan_part_kernel() {
    __shared__ int sh[SCAN_CHUNK];
    int t = threadIdx.x;
    int i = blockIdx.x * SCAN_CHUNK + t;
    int v = (i < NN) ? g_deg_in[i] : 0;
    sh[t] = v;
    __syncthreads();
    for (int off = 1; off < SCAN_CHUNK; off <<= 1) {
        int add = (t >= off) ? sh[t - off] : 0;
        __syncthreads();
        sh[t] += add;
        __syncthreads();
    }
    if (i < NN) g_rowptr[i + 1] = sh[t];   // local inclusive
    if (t == SCAN_CHUNK - 1) g_blocksums[blockIdx.x] = sh[t];
}

__global__ void scan_block_kernel(int nblocks) {
    __shared__ int sh[128];
    int t = threadIdx.x;
    int v = (t < nblocks) ? g_blocksums[t] : 0;
    sh[t] = v;
    __syncthreads();
    for (int off = 1; off < 128; off <<= 1) {
        int add = (t >= off) ? sh[t - off] : 0;
        __syncthreads();
        sh[t] += add;
        __syncthreads();
    }
    if (t < nblocks) g_blocksums[t] = sh[t];  // inclusive
}

__global__ void scan_add_kernel() {
    int t = threadIdx.x;
    int b = blockIdx.x;
    int i = b * SCAN_CHUNK + t;
    int off = (b > 0) ? g_blocksums[b - 1] : 0;
    if (i < NN) g_rowptr[i + 1] += off;
    if (b == 0 && t == 0) g_rowptr[0] = 0;
}

__global__ void fill_csr_kernel(const int* __restrict__ src, const int* __restrict__ dst) {
    int e = blockIdx.x * blockDim.x + threadIdx.x;
    if (e < EE) {
        int d = dst[e];
        int p = g_rowptr[d] + atomicAdd(&g_cursor[d], 1);
        g_col[p] = src[e];
    }
}

// ---------------- SpMM: m[dst] = norm_d[dst] * sum_{e: dst} norm_s[src]*x[src] ----------------
__global__ void __launch_bounds__(256) spmm_kernel(const float* __restrict__ X,
                                                   float* __restrict__ Mo) {
    int wg = (blockIdx.x * blockDim.x + threadIdx.x) >> 5;
    if (wg >= NN) return;
    int lane = threadIdx.x & 31;
    int s0 = g_rowptr[wg], s1 = g_rowptr[wg + 1];
    float4 a0 = {0, 0, 0, 0}, a1 = {0, 0, 0, 0};
    for (int e = s0; e < s1; e++) {
        int s = g_col[e];
        float ns = g_norm_s[s];
        const float4* xp = (const float4*)(X + (size_t)s * DD);
        float4 v0 = __ldg(xp + lane);
        float4 v1 = __ldg(xp + lane + 32);
        a0.x += v0.x * ns; a0.y += v0.y * ns; a0.z += v0.z * ns; a0.w += v0.w * ns;
        a1.x += v1.x * ns; a1.y += v1.y * ns; a1.z += v1.z * ns; a1.w += v1.w * ns;
    }
    float nd = g_norm_d[wg];
    a0.x *= nd; a0.y *= nd; a0.z *= nd; a0.w *= nd;
    a1.x *= nd; a1.y *= nd; a1.z *= nd; a1.w *= nd;
    float4* mp = (float4*)(Mo + (size_t)wg * DD);
    mp[lane] = a0;
    mp[lane + 32] = a1;
}

// ---------------- SGEMM: C[M,Np] = A[M,K] @ B[K,Np] + bias ----------------
#define BM 128
#define BN 128
#define BK 8
__global__ void __launch_bounds__(256) sgemm_bias_kernel(
    const float* __restrict__ A, const float* __restrict__ B,
    const float* __restrict__ bias, float* __restrict__ C,
    int M, int Np, int K) {
    __shared__ float As[BK][BM];
    __shared__ float Bs[BK][BN];
    int tid = threadIdx.x;
    int bm = blockIdx.x * BM;
    int bn = blockIdx.y * BN;

    int a_row = tid >> 1;
    int a_col = (tid & 1) * 4;
    int b_row = tid >> 5;
    int b_col = (tid & 31) * 4;

    int warp = tid >> 5;
    int lane = tid & 31;
    int tm = (warp >> 2) * 64 + (lane >> 2) * 8;
    int tn = (warp & 3) * 32 + (lane & 3) * 8;

    float acc[8][8];
#pragma unroll
    for (int i = 0; i < 8; i++)
#pragma unroll
        for (int j = 0; j < 8; j++) acc[i][j] = 0.f;

    for (int k0 = 0; k0 < K; k0 += BK) {
        float4 av = {0, 0, 0, 0};
        int ar = bm + a_row;
        if (ar < M) av = *(const float4*)(A + (size_t)ar * K + k0 + a_col);
        As[a_col + 0][a_row] = av.x;
        As[a_col + 1][a_row] = av.y;
        As[a_col + 2][a_row] = av.z;
        As[a_col + 3][a_row] = av.w;
        float4 bv = {0, 0, 0, 0};
        int bc = bn + b_col;
        if (bc < Np) bv = *(const float4*)(B + (size_t)(k0 + b_row) * Np + bc);
        *(float4*)&Bs[b_row][b_col] = bv;
        __syncthreads();
#pragma unroll
        for (int k = 0; k < BK; k++) {
            float a[8], b[8];
            *(float4*)&a[0] = *(const float4*)&As[k][tm];
            *(float4*)&a[4] = *(const float4*)&As[k][tm + 4];
            *(float4*)&b[0] = *(const float4*)&Bs[k][tn];
            *(float4*)&b[4] = *(const float4*)&Bs[k][tn + 4];
#pragma unroll
            for (int i = 0; i < 8; i++)
#pragma unroll
                for (int j = 0; j < 8; j++) acc[i][j] += a[i] * b[j];
        }
        __syncthreads();
    }
#pragma unroll
    for (int i = 0; i < 8; i++) {
        int r = bm + tm + i;
        if (r >= M) continue;
#pragma unroll
        for (int j = 0; j < 8; j++) {
            int c = bn + tn + j;
            if (c < Np) C[(size_t)r * Np + c] = acc[i][j] + bias[c];
        }
    }
}

// ---------------- BatchNorm stats + BN+ELU ----------------
__global__ void bn_stats_kernel(const float* __restrict__ X) {
    int t = threadIdx.x;  // column 0..255
    float s = 0.f, q = 0.f;
    for (int r = blockIdx.x; r < NN; r += gridDim.x) {
        float v = X[(size_t)r * DD + t];
        s += v;
        q += v * v;
    }
    atomicAdd(&g_colsum[t], s);
    atomicAdd(&g_colsq[t], q);
}

__global__ void bn_elu_kernel(float* __restrict__ X,
                              const float* __restrict__ gamma,
                              const float* __restrict__ beta) {
    int idx = blockIdx.x * blockDim.x + threadIdx.x;
    int col = idx & (DD - 1);
    float mu = g_colsum[col] * (1.f / NN);
    float var = g_colsq[col] * (1.f / NN) - mu * mu;
    float inv = rsqrtf(var + 1e-5f);
    float y = gamma[col] * (X[idx] - mu) * inv + beta[col];
    X[idx] = (y > 0.f) ? y : expm1f(y);
}

// ---------------- launch ----------------
extern "C" void kernel_launch(void* const* d_in, const int* in_sizes, int n_in,
                              void* d_out, int out_size) {
    const float* feat  = (const float*)d_in[0];
    const int*   src   = (const int*)d_in[1];
    const int*   dst   = (const int*)d_in[2];
    const float* W_fc  = (const float*)d_in[3];
    const float* b_fc  = (const float*)d_in[4];
    const float* W1    = (const float*)d_in[5];
    const float* b1    = (const float*)d_in[6];
    const float* W2    = (const float*)d_in[7];
    const float* b2    = (const float*)d_in[8];
    const float* W3    = (const float*)d_in[9];
    const float* b3    = (const float*)d_in[10];
    const float* gamma = (const float*)d_in[11];
    const float* beta  = (const float*)d_in[12];
    const float* W_lin = (const float*)d_in[13];
    const float* b_lin = (const float*)d_in[14];

    float* out_x      = (float*)d_out;            // [NN, DD]
    float* out_logits = (float*)d_out + (size_t)NN * DD;  // [NN, CC]

    float* gx; cudaGetSymbolAddress((void**)&gx, g_x);
    float* gm; cudaGetSymbolAddress((void**)&gm, g_m);

    int nscan = (NN + SCAN_CHUNK - 1) / SCAN_CHUNK;

    // graph + norms + CSR build
    zero_init_kernel<<<(NN + 255) / 256, 256>>>();
    count_deg_kernel<<<(EE + 255) / 256, 256>>>(src, dst);
    norms_kernel<<<(NN + 255) / 256, 256>>>();
    scan_part_kernel<<<nscan, SCAN_CHUNK>>>();
    scan_block_kernel<<<1, 128>>>(nscan);
    scan_add_kernel<<<nscan, SCAN_CHUNK>>>();
    fill_csr_kernel<<<(EE + 255) / 256, 256>>>(src, dst);

    dim3 g_fc((NN + BM - 1) / BM, (DD + BN - 1) / BN);
    dim3 g_lin((NN + BM - 1) / BM, (CC + BN - 1) / BN);
    int spmm_blocks = (NN * 32 + 255) / 256;
    int elem_blocks = (NN * DD) / 256;

    // x = feat @ W_fc + b_fc
    sgemm_bias_kernel<<<g_fc, 256>>>(feat, W_fc, b_fc, gx, NN, DD, FF);

    // layer 1
    spmm_kernel<<<spmm_blocks, 256>>>(gx, gm);
    sgemm_bias_kernel<<<g_fc, 256>>>(gm, W1, b1, gx, NN, DD, DD);
    zero_bn_kernel<<<1, 256>>>();
    bn_stats_kernel<<<256, 256>>>(gx);
    bn_elu_kernel<<<elem_blocks, 256>>>(gx, gamma, beta);

    // layer 2
    spmm_kernel<<<spmm_blocks, 256>>>(gx, gm);
    sgemm_bias_kernel<<<g_fc, 256>>>(gm, W2, b2, gx, NN, DD, DD);
    zero_bn_kernel<<<1, 256>>>();
    bn_stats_kernel<<<256, 256>>>(gx);
    bn_elu_kernel<<<elem_blocks, 256>>>(gx, gamma, beta);

    // layer 3 (no BN) -> out_x
    spmm_kernel<<<spmm_blocks, 256>>>(gx, gm);
    sgemm_bias_kernel<<<g_fc, 256>>>(gm, W3, b3, out_x, NN, DD, DD);

    // logits = out_x @ W_lin + b_lin
    sgemm_bias_kernel<<<g_lin, 256>>>(out_x, W_lin, b_lin, out_logits, NN, CC, DD);
}

// round 3
// speedup vs baseline: 1.5363x; 1.5363x over previous
#include <cuda_runtime.h>
#include <cuda_bf16.h>
#include <math.h>
#include <stdint.h>

// Problem constants (fixed shapes from reference)
#define NN 50000
#define EE 300000
#define DD 256
#define FF 1024
#define CC 40

// ======================= helpers =======================
__device__ __forceinline__ uint32_t smem_u32(const void* p) {
    uint32_t a;
    asm("{ .reg .u64 t; cvta.to.shared.u64 t, %1; cvt.u32.u64 %0, t; }" : "=r"(a) : "l"(p));
    return a;
}

__device__ __forceinline__ void mma_bf16(float* c, const uint32_t* a, const uint32_t* b) {
    asm volatile(
        "mma.sync.aligned.m16n8k16.row.col.f32.bf16.bf16.f32 "
        "{%0,%1,%2,%3}, {%4,%5,%6,%7}, {%8,%9}, {%0,%1,%2,%3};"
        : "+f"(c[0]), "+f"(c[1]), "+f"(c[2]), "+f"(c[3])
        : "r"(a[0]), "r"(a[1]), "r"(a[2]), "r"(a[3]), "r"(b[0]), "r"(b[1]));
}

__device__ __forceinline__ void ldsm4(uint32_t* r, uint32_t addr) {
    asm volatile("ldmatrix.sync.aligned.m8n8.x4.shared.b16 {%0,%1,%2,%3}, [%4];"
                 : "=r"(r[0]), "=r"(r[1]), "=r"(r[2]), "=r"(r[3]) : "r"(addr));
}
__device__ __forceinline__ void ldsm4t(uint32_t* r, uint32_t addr) {
    asm volatile("ldmatrix.sync.aligned.m8n8.x4.trans.shared.b16 {%0,%1,%2,%3}, [%4];"
                 : "=r"(r[0]), "=r"(r[1]), "=r"(r[2]), "=r"(r[3]) : "r"(addr));
}

__device__ __forceinline__ uint32_t packbf(float x, float y) {
    __nv_bfloat162 t = __floats2bfloat162_rn(x, y);   // .x (low 16) = x
    return *reinterpret_cast<uint32_t*>(&t);
}

// split float4 pair -> 2 hi-packed words, 2 lo-packed words
__device__ __forceinline__ void split4(float4 v, uint32_t* hi, uint32_t* lo) {
    float hx = __bfloat162float(__float2bfloat16(v.x));
    float hy = __bfloat162float(__float2bfloat16(v.y));
    float hz = __bfloat162float(__float2bfloat16(v.z));
    float hw = __bfloat162float(__float2bfloat16(v.w));
    hi[0] = packbf(v.x, v.y);
    hi[1] = packbf(v.z, v.w);
    lo[0] = packbf(v.x - hx, v.y - hy);
    lo[1] = packbf(v.z - hz, v.w - hw);
}

// ======================= device scratch =======================
__device__ float g_x[NN * DD];
__device__ float g_m[NN * DD];
__device__ float g_norm_s[NN];
__device__ float g_norm_d[NN];
__device__ int   g_deg_out[NN];
__device__ int   g_deg_in[NN];
__device__ int   g_rowptr[NN + 1];
__device__ int   g_cursor[NN];
__device__ int   g_col[EE];
__device__ int   g_blocksums[128];
__device__ float g_colsum[DD];
__device__ float g_colsq[DD];

// ======================= utility kernels =======================
__global__ void zero_init_kernel() {
    int i = blockIdx.x * blockDim.x + threadIdx.x;
    if (i < NN) { g_deg_out[i] = 0; g_deg_in[i] = 0; g_cursor[i] = 0; }
}
__global__ void zero_bn_kernel() {
    int t = threadIdx.x;
    if (t < DD) { g_colsum[t] = 0.f; g_colsq[t] = 0.f; }
}
__global__ void count_deg_kernel(const int* __restrict__ src, const int* __restrict__ dst) {
    int e = blockIdx.x * blockDim.x + threadIdx.x;
    if (e < EE) {
        atomicAdd(&g_deg_out[src[e]], 1);
        atomicAdd(&g_deg_in[dst[e]], 1);
    }
}
__global__ void norms_kernel() {
    int i = blockIdx.x * blockDim.x + threadIdx.x;
    if (i < NN) {
        g_norm_s[i] = rsqrtf(fmaxf((float)g_deg_out[i], 1.f));
        g_norm_d[i] = rsqrtf(fmaxf((float)g_deg_in[i], 1.f));
    }
}

#define SCAN_CHUNK 512
__global__ void scan_part_kernel() {
    __shared__ int sh[SCAN_CHUNK];
    int t = threadIdx.x;
    int i = blockIdx.x * SCAN_CHUNK + t;
    int v = (i < NN) ? g_deg_in[i] : 0;
    sh[t] = v;
    __syncthreads();
    for (int off = 1; off < SCAN_CHUNK; off <<= 1) {
        int add = (t >= off) ? sh[t - off] : 0;
        __syncthreads();
        sh[t] += add;
        __syncthreads();
    }
    if (i < NN) g_rowptr[i + 1] = sh[t];
    if (t == SCAN_CHUNK - 1) g_blocksums[blockIdx.x] = sh[t];
}
__global__ void scan_block_kernel(int nblocks) {
    __shared__ int sh[128];
    int t = threadIdx.x;
    int v = (t < nblocks) ? g_blocksums[t] : 0;
    sh[t] = v;
    __syncthreads();
    for (int off = 1; off < 128; off <<= 1) {
        int add = (t >= off) ? sh[t - off] : 0;
        __syncthreads();
        sh[t] += add;
        __syncthreads();
    }
    if (t < nblocks) g_blocksums[t] = sh[t];
}
__global__ void scan_add_kernel() {
    int t = threadIdx.x;
    int b = blockIdx.x;
    int i = b * SCAN_CHUNK + t;
    int off = (b > 0) ? g_blocksums[b - 1] : 0;
    if (i < NN) g_rowptr[i + 1] += off;
    if (b == 0 && t == 0) g_rowptr[0] = 0;
}
__global__ void fill_csr_kernel(const int* __restrict__ src, const int* __restrict__ dst) {
    int e = blockIdx.x * blockDim.x + threadIdx.x;
    if (e < EE) {
        int d = dst[e];
        int p = g_rowptr[d] + atomicAdd(&g_cursor[d], 1);
        g_col[p] = src[e];
    }
}

// ---------------- SpMM ----------------
__global__ void __launch_bounds__(256) spmm_kernel(const float* __restrict__ X,
                                                   float* __restrict__ Mo) {
    int wg = (blockIdx.x * blockDim.x + threadIdx.x) >> 5;
    if (wg >= NN) return;
    int lane = threadIdx.x & 31;
    int s0 = g_rowptr[wg], s1 = g_rowptr[wg + 1];
    float4 a0 = {0, 0, 0, 0}, a1 = {0, 0, 0, 0};
    for (int e = s0; e < s1; e++) {
        int s = g_col[e];
        float ns = g_norm_s[s];
        const float4* xp = (const float4*)(X + (size_t)s * DD);
        float4 v0 = __ldg(xp + lane);
        float4 v1 = __ldg(xp + lane + 32);
        a0.x += v0.x * ns; a0.y += v0.y * ns; a0.z += v0.z * ns; a0.w += v0.w * ns;
        a1.x += v1.x * ns; a1.y += v1.y * ns; a1.z += v1.z * ns; a1.w += v1.w * ns;
    }
    float nd = g_norm_d[wg];
    a0.x *= nd; a0.y *= nd; a0.z *= nd; a0.w *= nd;
    a1.x *= nd; a1.y *= nd; a1.z *= nd; a1.w *= nd;
    float4* mp = (float4*)(Mo + (size_t)wg * DD);
    mp[lane] = a0;
    mp[lane + 32] = a1;
}

// ---------------- BatchNorm ----------------
__global__ void bn_stats_kernel(const float* __restrict__ X) {
    int t = threadIdx.x;
    float s = 0.f, q = 0.f;
    for (int r = blockIdx.x; r < NN; r += gridDim.x) {
        float v = X[(size_t)r * DD + t];
        s += v;
        q += v * v;
    }
    atomicAdd(&g_colsum[t], s);
    atomicAdd(&g_colsq[t], q);
}
__global__ void bn_elu_kernel(float* __restrict__ X,
                              const float* __restrict__ gamma,
                              const float* __restrict__ beta) {
    int idx = blockIdx.x * blockDim.x + threadIdx.x;
    int col = idx & (DD - 1);
    float mu = g_colsum[col] * (1.f / NN);
    float var = g_colsq[col] * (1.f / NN) - mu * mu;
    float inv = rsqrtf(var + 1e-5f);
    float y = gamma[col] * (X[idx] - mu) * inv + beta[col];
    X[idx] = (y > 0.f) ? y : expm1f(y);
}

// ======================= bf16x3 mma.sync GEMM =======================
// C[M,N] = A[M,K] @ B[K,N] + bias.  CTA tile 128x128, 8 warps (4M x 2N),
// warp tile 32x64 via m16n8k16. Split precision: A,B -> hi+lo bf16;
// acc += Ah*Bh + Ah*Bl + Al*Bh (fp32 accumulate).
#define SA_STRIDE 80    // bytes per A smem row (32 bf16 + pad)
#define SB_STRIDE 272   // bytes per B smem row (128 bf16 + pad)

__global__ void __launch_bounds__(256) gemm_mma_kernel(
    const float* __restrict__ A, const float* __restrict__ B,
    const float* __restrict__ bias, float* __restrict__ C,
    int M, int N, int K)
{
    __shared__ __align__(16) uint8_t sAhi[128 * SA_STRIDE];
    __shared__ __align__(16) uint8_t sAlo[128 * SA_STRIDE];
    __shared__ __align__(16) uint8_t sBhi[32 * SB_STRIDE];
    __shared__ __align__(16) uint8_t sBlo[32 * SB_STRIDE];

    const int tid = threadIdx.x;
    const int wid = tid >> 5;
    const int lane = tid & 31;
    const int warpM = (wid & 3) * 32;
    const int warpN = (wid >> 2) * 64;
    const int bm = blockIdx.x * 128;
    const int bn = blockIdx.y * 128;

    const uint32_t uAhi = smem_u32(sAhi);
    const uint32_t uAlo = smem_u32(sAlo);
    const uint32_t uBhi = smem_u32(sBhi);
    const uint32_t uBlo = smem_u32(sBlo);

    // per-lane ldmatrix sub-offsets
    const int m8 = lane >> 3;       // which 8x8 submatrix this lane addresses
    const int r8 = lane & 7;
    const uint32_t aoff = (uint32_t)(((m8 & 1) * 8 + r8) * SA_STRIDE + (m8 >> 1) * 16);
    const uint32_t boff = (uint32_t)(((m8 & 1) * 8 + r8) * SB_STRIDE + (m8 >> 1) * 16);

    float acc[2][8][4];
#pragma unroll
    for (int i = 0; i < 2; i++)
#pragma unroll
        for (int j = 0; j < 8; j++)
#pragma unroll
            for (int q = 0; q < 4; q++) acc[i][j][q] = 0.f;

    // gmem load assignments
    const int arow = tid >> 1;                 // 0..127
    const int acb  = (tid & 1) * 16;           // 0 or 16
    const int bkr  = tid >> 3;                 // 0..31
    const int bcb  = (tid & 7) * 16;           // 0..112

    for (int k0 = 0; k0 < K; k0 += 32) {
        // ---- A tile 128x32 ----
        {
            float4 f[4];
            if (bm + arow < M) {
                const float4* p = (const float4*)(A + (size_t)(bm + arow) * K + k0 + acb);
#pragma unroll
                for (int q = 0; q < 4; q++) f[q] = __ldg(p + q);
            } else {
#pragma unroll
                for (int q = 0; q < 4; q++) f[q] = make_float4(0.f, 0.f, 0.f, 0.f);
            }
            uint32_t hi[8], lo[8];
#pragma unroll
            for (int q = 0; q < 4; q++) split4(f[q], hi + 2 * q, lo + 2 * q);
            uint8_t* dh = sAhi + arow * SA_STRIDE + acb * 2;
            uint8_t* dl = sAlo + arow * SA_STRIDE + acb * 2;
            *(uint4*)dh        = make_uint4(hi[0], hi[1], hi[2], hi[3]);
            *(uint4*)(dh + 16) = make_uint4(hi[4], hi[5], hi[6], hi[7]);
            *(uint4*)dl        = make_uint4(lo[0], lo[1], lo[2], lo[3]);
            *(uint4*)(dl + 16) = make_uint4(lo[4], lo[5], lo[6], lo[7]);
        }
        // ---- B tile 32x128 ----
        {
            float4 f[4];
            const size_t brow = (size_t)(k0 + bkr) * N;
            if (bn + bcb + 15 < N) {
                const float4* p = (const float4*)(B + brow + bn + bcb);
#pragma unroll
                for (int q = 0; q < 4; q++) f[q] = __ldg(p + q);
            } else {
                float v[16];
#pragma unroll
                for (int i = 0; i < 16; i++) {
                    int c = bn + bcb + i;
                    v[i] = (c < N) ? __ldg(B + brow + c) : 0.f;
                }
#pragma unroll
                for (int q = 0; q < 4; q++) f[q] = make_float4(v[4*q], v[4*q+1], v[4*q+2], v[4*q+3]);
            }
            uint32_t hi[8], lo[8];
#pragma unroll
            for (int q = 0; q < 4; q++) split4(f[q], hi + 2 * q, lo + 2 * q);
            uint8_t* dh = sBhi + bkr * SB_STRIDE + bcb * 2;
            uint8_t* dl = sBlo + bkr * SB_STRIDE + bcb * 2;
            *(uint4*)dh        = make_uint4(hi[0], hi[1], hi[2], hi[3]);
            *(uint4*)(dh + 16) = make_uint4(hi[4], hi[5], hi[6], hi[7]);
            *(uint4*)dl        = make_uint4(lo[0], lo[1], lo[2], lo[3]);
            *(uint4*)(dl + 16) = make_uint4(lo[4], lo[5], lo[6], lo[7]);
        }
        __syncthreads();

#pragma unroll
        for (int kh = 0; kh < 2; kh++) {
            uint32_t afrag[2][4];
            uint32_t bh[16], bl[16];
            const uint32_t aW = (uint32_t)(warpM * SA_STRIDE + kh * 32) + aoff;
            const uint32_t bW = (uint32_t)(kh * 16 * SB_STRIDE + warpN * 2) + boff;
            // load A_hi, B_hi
#pragma unroll
            for (int mt = 0; mt < 2; mt++)
                ldsm4(afrag[mt], uAhi + aW + mt * 16 * SA_STRIDE);
#pragma unroll
            for (int p = 0; p < 4; p++)
                ldsm4t(&bh[4 * p], uBhi + bW + p * 32);
            // pass 1: Ah * Bh
#pragma unroll
            for (int mt = 0; mt < 2; mt++)
#pragma unroll
                for (int nt = 0; nt < 8; nt++)
                    mma_bf16(acc[mt][nt], afrag[mt], &bh[nt * 2]);
            // load B_lo, pass 2: Ah * Bl
#pragma unroll
            for (int p = 0; p < 4; p++)
                ldsm4t(&bl[4 * p], uBlo + bW + p * 32);
#pragma unroll
            for (int mt = 0; mt < 2; mt++)
#pragma unroll
                for (int nt = 0; nt < 8; nt++)
                    mma_bf16(acc[mt][nt], afrag[mt], &bl[nt * 2]);
            // load A_lo (overwrite), pass 3: Al * Bh
#pragma unroll
            for (int mt = 0; mt < 2; mt++)
                ldsm4(afrag[mt], uAlo + aW + mt * 16 * SA_STRIDE);
#pragma unroll
            for (int mt = 0; mt < 2; mt++)
#pragma unroll
                for (int nt = 0; nt < 8; nt++)
                    mma_bf16(acc[mt][nt], afrag[mt], &bh[nt * 2]);
        }
        __syncthreads();
    }

    // ---- epilogue ----
    const int g  = lane >> 2;
    const int tg = lane & 3;
#pragma unroll
    for (int mt = 0; mt < 2; mt++) {
        int row0 = bm + warpM + mt * 16 + g;
        int row1 = row0 + 8;
#pragma unroll
        for (int nt = 0; nt < 8; nt++) {
            int col0 = bn + warpN + nt * 8 + tg * 2;
            if (col0 < N) {
                float bi0 = __ldg(bias + col0);
                bool c1ok = (col0 + 1 < N);
                float bi1 = c1ok ? __ldg(bias + col0 + 1) : 0.f;
                if (row0 < M) {
                    C[(size_t)row0 * N + col0] = acc[mt][nt][0] + bi0;
                    if (c1ok) C[(size_t)row0 * N + col0 + 1] = acc[mt][nt][1] + bi1;
                }
                if (row1 < M) {
                    C[(size_t)row1 * N + col0] = acc[mt][nt][2] + bi0;
                    if (c1ok) C[(size_t)row1 * N + col0 + 1] = acc[mt][nt][3] + bi1;
                }
            }
        }
    }
}

// ======================= launch =======================
extern "C" void kernel_launch(void* const* d_in, const int* in_sizes, int n_in,
                              void* d_out, int out_size) {
    const float* feat  = (const float*)d_in[0];
    const int*   src   = (const int*)d_in[1];
    const int*   dst   = (const int*)d_in[2];
    const float* W_fc  = (const float*)d_in[3];
    const float* b_fc  = (const float*)d_in[4];
    const float* W1    = (const float*)d_in[5];
    const float* b1    = (const float*)d_in[6];
    const float* W2    = (const float*)d_in[7];
    const float* b2    = (const float*)d_in[8];
    const float* W3    = (const float*)d_in[9];
    const float* b3    = (const float*)d_in[10];
    const float* gamma = (const float*)d_in[11];
    const float* beta  = (const float*)d_in[12];
    const float* W_lin = (const float*)d_in[13];
    const float* b_lin = (const float*)d_in[14];

    float* out_x      = (float*)d_out;
    float* out_logits = (float*)d_out + (size_t)NN * DD;

    float* gx; cudaGetSymbolAddress((void**)&gx, g_x);
    float* gm; cudaGetSymbolAddress((void**)&gm, g_m);

    int nscan = (NN + SCAN_CHUNK - 1) / SCAN_CHUNK;

    zero_init_kernel<<<(NN + 255) / 256, 256>>>();
    count_deg_kernel<<<(EE + 255) / 256, 256>>>(src, dst);
    norms_kernel<<<(NN + 255) / 256, 256>>>();
    scan_part_kernel<<<nscan, SCAN_CHUNK>>>();
    scan_block_kernel<<<1, 128>>>(nscan);
    scan_add_kernel<<<nscan, SCAN_CHUNK>>>();
    fill_csr_kernel<<<(EE + 255) / 256, 256>>>(src, dst);

    const int MT = (NN + 127) / 128;   // 391
    dim3 g_fc(MT, 2);    // N=256
    dim3 g_lin(MT, 1);   // N=40
    int spmm_blocks = (NN * 32 + 255) / 256;
    int elem_blocks = (NN * DD) / 256;

    // x = feat @ W_fc + b_fc
    gemm_mma_kernel<<<g_fc, 256>>>(feat, W_fc, b_fc, gx, NN, DD, FF);

    // layer 1
    spmm_kernel<<<spmm_blocks, 256>>>(gx, gm);
    gemm_mma_kernel<<<g_fc, 256>>>(gm, W1, b1, gx, NN, DD, DD);
    zero_bn_kernel<<<1, 256>>>();
    bn_stats_kernel<<<256, 256>>>(gx);
    bn_elu_kernel<<<elem_blocks, 256>>>(gx, gamma, beta);

    // layer 2
    spmm_kernel<<<spmm_blocks, 256>>>(gx, gm);
    gemm_mma_kernel<<<g_fc, 256>>>(gm, W2, b2, gx, NN, DD, DD);
    zero_bn_kernel<<<1, 256>>>();
    bn_stats_kernel<<<256, 256>>>(gx);
    bn_elu_kernel<<<elem_blocks, 256>>>(gx, gamma, beta);

    // layer 3 (no BN) -> out_x
    spmm_kernel<<<spmm_blocks, 256>>>(gx, gm);
    gemm_mma_kernel<<<g_fc, 256>>>(gm, W3, b3, out_x, NN, DD, DD);

    // logits = out_x @ W_lin + b_lin
    gemm_mma_kernel<<<g_lin, 256>>>(out_x, W_lin, b_lin, out_logits, NN, CC, DD);
}